// round 11
// baseline (speedup 1.0000x reference)
#include <cuda_runtime.h>
#include <cuda_bf16.h>
#include <cstdint>

#define N_NODES 50000
#define N_EDGES 800000
#define F_DIM   512
#define F_OUT   256

// ---------------- persistent device scratch ----------------
__device__ float g_H[(size_t)N_NODES * F_DIM];
__device__ float g_X[(size_t)N_NODES * F_DIM];
__device__ float g_Wt0[512 * 512];
__device__ float g_Wt1[512 * 512];
__device__ float g_Wt2[512 * 256];
__device__ int   g_cnt_out[N_NODES];
__device__ int   g_cnt_in[N_NODES];
__device__ float g_in_norm[N_NODES];
__device__ int   g_row_ptr[N_NODES + 1];
__device__ int   g_cursor[N_NODES];
__device__ int   g_esrc[N_EDGES];
__device__ int   g_is64;

__device__ __forceinline__ float rna_tf32(float x) {
    float r;
    asm("cvt.rna.tf32.f32 %0, %1;" : "=f"(r) : "f"(x));
    return r;
}
__device__ __forceinline__ int load_idx(const void* p, int i) {
    if (g_is64) return (int)((const long long*)p)[i];
    return ((const int*)p)[i];
}

// ============== prep: all 3 weight transposes (+tf32 round) ==============
__global__ void transpose_all_kernel(const float* __restrict__ W0, float* __restrict__ Wt0,
                                     const float* __restrict__ W1, float* __restrict__ Wt1,
                                     const float* __restrict__ W2, float* __restrict__ Wt2) {
    const float* W; float* Wt; int N;
    if (blockIdx.z == 0)      { W = W0; Wt = Wt0; N = 512; }
    else if (blockIdx.z == 1) { W = W1; Wt = Wt1; N = 512; }
    else                      { W = W2; Wt = Wt2; N = 256; if ((int)blockIdx.x >= 8) return; }
    __shared__ float tile[32][33];
    int n = blockIdx.x * 32 + threadIdx.x;
    int k = blockIdx.y * 32 + threadIdx.y;
    #pragma unroll
    for (int dy = 0; dy < 32; dy += 8)
        tile[threadIdx.y + dy][threadIdx.x] = W[(size_t)(k + dy) * N + n];
    __syncthreads();
    int n2 = blockIdx.x * 32 + threadIdx.y;
    int k2 = blockIdx.y * 32 + threadIdx.x;
    #pragma unroll
    for (int dy = 0; dy < 32; dy += 8)
        Wt[(size_t)(n2 + dy) * 512 + k2] = rna_tf32(tile[threadIdx.x][threadIdx.y + dy]);
}

// ============== prep: detect dtype + zero counts ==============
__global__ void detect_zero_kernel(const int* p) {
    int i = blockIdx.x * blockDim.x + threadIdx.x;
    if (i < N_NODES) { g_cnt_out[i] = 0; g_cnt_in[i] = 0; }
    if (blockIdx.x == 0 && threadIdx.x == 0) {
        int all0 = 1;
        for (int j = 1; j < 256; j += 2)
            if (p[j] != 0) { all0 = 0; break; }
        g_is64 = all0;
    }
}

// ============== prep: degrees ==============
__global__ void degree_kernel(const void* src, const void* dst) {
    int stride = gridDim.x * blockDim.x;
    for (int e = blockIdx.x * blockDim.x + threadIdx.x; e < N_EDGES; e += stride) {
        atomicAdd(&g_cnt_out[load_idx(src, e)], 1);
        atomicAdd(&g_cnt_in[load_idx(dst, e)], 1);
    }
}

// ============== prep: in_norm + row_ptr scan (1 block, 1024 thr) ==============
__global__ void norm_scan_kernel() {
    const int PER = (N_NODES + 1023) / 1024;   // 49
    __shared__ int wsum[32];
    int t = threadIdx.x;
    int lane = t & 31, wid = t >> 5;
    int start = t * PER;
    int end = start + PER; if (end > N_NODES) end = N_NODES;

    int sum = 0;
    for (int i = start; i < end; i++) {
        int ci = g_cnt_in[i]; if (ci < 1) ci = 1;
        g_in_norm[i] = rsqrtf((float)ci);
        sum += g_cnt_in[i];
    }
    int v = sum;
    #pragma unroll
    for (int o = 1; o < 32; o <<= 1) {
        int u = __shfl_up_sync(0xFFFFFFFFu, v, o);
        if (lane >= o) v += u;
    }
    if (lane == 31) wsum[wid] = v;
    __syncthreads();
    if (wid == 0) {
        int w = wsum[lane];
        #pragma unroll
        for (int o = 1; o < 32; o <<= 1) {
            int u = __shfl_up_sync(0xFFFFFFFFu, w, o);
            if (lane >= o) w += u;
        }
        wsum[lane] = w;
    }
    __syncthreads();
    int base = (wid > 0) ? wsum[wid - 1] : 0;
    int run = base + v - sum;
    for (int i = start; i < end; i++) {
        g_row_ptr[i] = run;
        g_cursor[i]  = run;
        run += g_cnt_in[i];
    }
    if (t == 1023) g_row_ptr[N_NODES] = run;
}

// ============== prep: CSR fill ==============
__global__ void fill_kernel(const void* src, const void* dst) {
    int stride = gridDim.x * blockDim.x;
    for (int e = blockIdx.x * blockDim.x + threadIdx.x; e < N_EDGES; e += stride) {
        int d = load_idx(dst, e);
        int pos = atomicAdd(&g_cursor[d], 1);
        g_esrc[pos] = load_idx(src, e);
    }
}

// ============================ tf32 mma.sync GEMM ============================
// H[m, n] = (sum_k X[m,k] * Wt[n,k]) * rsqrt(max(cnt_out[m],1))
// BM=256, BN=128, BK=32, 256 thr, warp grid 4x2, warp tile 64x64, LDSM frags,
// 4-stage cp.async ring (prefetch depth 3) to hide global-load latency at 1 CTA/SM.
#define BK        32
#define ROW_STR   36
#define A_FLOATS  (256 * ROW_STR)            // 9216
#define B_FLOATS  (128 * ROW_STR)            // 4608
#define STAGE_FLOATS (A_FLOATS + B_FLOATS)   // 13824
#define N_STAGES  4
#define SMEM_GEMM (N_STAGES * STAGE_FLOATS * 4)  // 221184 B

__device__ __forceinline__ uint32_t smem_u32(const void* p) {
    uint32_t a;
    asm("{ .reg .u64 t; cvta.to.shared.u64 t, %1; cvt.u32.u64 %0, t; }" : "=r"(a) : "l"(p));
    return a;
}
__device__ __forceinline__ void cp_async16(uint32_t dst, const void* src) {
    asm volatile("cp.async.ca.shared.global [%0], [%1], 16;" :: "r"(dst), "l"(src));
}
__device__ __forceinline__ void ldsm_x4(uint32_t& r0, uint32_t& r1, uint32_t& r2, uint32_t& r3,
                                        uint32_t addr) {
    asm volatile("ldmatrix.sync.aligned.m8n8.x4.shared.b16 {%0,%1,%2,%3}, [%4];"
        : "=r"(r0), "=r"(r1), "=r"(r2), "=r"(r3) : "r"(addr));
}
__device__ __forceinline__ void mma_tf32(float c[4],
                                         uint32_t a0, uint32_t a1, uint32_t a2, uint32_t a3,
                                         uint32_t b0, uint32_t b1) {
    asm volatile("mma.sync.aligned.m16n8k8.row.col.f32.tf32.tf32.f32 "
        "{%0,%1,%2,%3}, {%4,%5,%6,%7}, {%8,%9}, {%0,%1,%2,%3};"
        : "+f"(c[0]), "+f"(c[1]), "+f"(c[2]), "+f"(c[3])
        : "r"(a0), "r"(a1), "r"(a2), "r"(a3), "r"(b0), "r"(b1));
}
__device__ __forceinline__ uint32_t cvt_bits_tf32(uint32_t u) {
    return __float_as_uint(rna_tf32(__uint_as_float(u)));
}
__device__ __forceinline__ float out_norm_of(int row) {
    int co = g_cnt_out[row]; if (co < 1) co = 1;
    return rsqrtf((float)co);
}

template <bool CVTA>
__global__ __launch_bounds__(256)
void gemm_tf32_mma(const float* __restrict__ X, const float* __restrict__ Wt,
                   float* __restrict__ H, int M, int N) {
    extern __shared__ float smem[];
    uint32_t sbase = smem_u32(smem);
    int tid  = threadIdx.x;
    int wid  = tid >> 5;
    int lane = tid & 31;
    int m0 = blockIdx.y * 256;
    int n0 = blockIdx.x * 128;

    int wm = wid >> 1;       // 0..3 -> 64-row m tiles
    int wn = wid & 1;        // 0..1 -> 64-col n tiles
    int qrow = lane >> 2;
    int qk   = lane & 3;

    int cr = tid >> 3;       // 0..31
    int cc = tid & 7;

    // LDSM per-lane byte offsets (within stage) — verified rounds 6/7/10
    uint32_t pa_off = (uint32_t)(((wm * 64 + (lane & 15)) * ROW_STR + ((lane >> 4) << 2)) * 4);
    uint32_t pb_off = (uint32_t)(((wn * 64 + ((lane >> 4) << 3) + (lane & 7)) * ROW_STR
                                  + (((lane >> 3) & 1) << 2)) * 4) + A_FLOATS * 4;

    float acc[4][8][4];
    #pragma unroll
    for (int i = 0; i < 4; i++)
        #pragma unroll
        for (int j = 0; j < 8; j++)
            #pragma unroll
            for (int q = 0; q < 4; q++) acc[i][j][q] = 0.f;

    const int n_chunks = 512 / BK;   // 16

    // prefetch issue for chunk j into stage j & 3 (one commit group per chunk)
    auto issue_chunk = [&](int j) {
        int k0 = j * BK;
        int st = j & (N_STAGES - 1);
        uint32_t aS = sbase + (uint32_t)(st * STAGE_FLOATS * 4);
        uint32_t bS = aS + A_FLOATS * 4;
        float* aF = smem + st * STAGE_FLOATS;
        #pragma unroll
        for (int pass = 0; pass < 8; pass++) {
            int r = cr + pass * 32;
            int grow = m0 + r;
            uint32_t adst = aS + (uint32_t)((r * ROW_STR + cc * 4) * 4);
            if (grow < M) cp_async16(adst, &X[(size_t)grow * 512 + k0 + cc * 4]);
            else *reinterpret_cast<float4*>(&aF[r * ROW_STR + cc * 4]) = make_float4(0,0,0,0);
        }
        #pragma unroll
        for (int pass = 0; pass < 4; pass++) {
            int r = cr + pass * 32;
            uint32_t bdst = bS + (uint32_t)((r * ROW_STR + cc * 4) * 4);
            cp_async16(bdst, &Wt[(size_t)(n0 + r) * 512 + k0 + cc * 4]);
        }
        asm volatile("cp.async.commit_group;");
    };

    // prologue: fill 3 stages ahead
    issue_chunk(0);
    issue_chunk(1);
    issue_chunk(2);

    for (int i = 0; i < n_chunks; i++) {
        // wait until chunk i's group is complete (pending = chunks i..min(i+2,15))
        if (i <= 13)      asm volatile("cp.async.wait_group 2;");
        else if (i == 14) asm volatile("cp.async.wait_group 1;");
        else              asm volatile("cp.async.wait_group 0;");
        __syncthreads();   // make all threads' copies visible + stage-reuse barrier

        if (i + 3 < n_chunks) issue_chunk(i + 3);

        uint32_t stage = (uint32_t)((i & (N_STAGES - 1)) * STAGE_FLOATS * 4);
        uint32_t paS = sbase + stage + pa_off;
        uint32_t pbS = sbase + stage + pb_off;

        #pragma unroll
        for (int kb = 0; kb < BK; kb += 8) {
            uint32_t af[4][4];
            #pragma unroll
            for (int mf = 0; mf < 4; mf++) {
                ldsm_x4(af[mf][0], af[mf][1], af[mf][2], af[mf][3],
                        paS + (uint32_t)((mf * 16 * ROW_STR + kb) * 4));
                if (CVTA) {
                    af[mf][0] = cvt_bits_tf32(af[mf][0]);
                    af[mf][1] = cvt_bits_tf32(af[mf][1]);
                    af[mf][2] = cvt_bits_tf32(af[mf][2]);
                    af[mf][3] = cvt_bits_tf32(af[mf][3]);
                }
            }
            uint32_t bf[8][2];
            #pragma unroll
            for (int f = 0; f < 4; f++) {
                ldsm_x4(bf[2*f][0], bf[2*f][1], bf[2*f+1][0], bf[2*f+1][1],
                        pbS + (uint32_t)((f * 16 * ROW_STR + kb) * 4));
            }
            #pragma unroll
            for (int mf = 0; mf < 4; mf++)
                #pragma unroll
                for (int nf = 0; nf < 8; nf++)
                    mma_tf32(acc[mf][nf], af[mf][0], af[mf][1], af[mf][2], af[mf][3],
                             bf[nf][0], bf[nf][1]);
        }
    }

    // epilogue: scale by out_norm (computed inline from degree counters), store
    #pragma unroll
    for (int mf = 0; mf < 4; mf++) {
        int row  = m0 + wm * 64 + mf * 16 + qrow;
        int row8 = row + 8;
        float s0 = (row  < M) ? out_norm_of(row)  : 0.f;
        float s1 = (row8 < M) ? out_norm_of(row8) : 0.f;
        #pragma unroll
        for (int nf = 0; nf < 8; nf++) {
            int col = n0 + wn * 64 + nf * 8 + qk * 2;
            if (row < M) {
                float2 v = make_float2(acc[mf][nf][0] * s0, acc[mf][nf][1] * s0);
                *reinterpret_cast<float2*>(&H[(size_t)row * N + col]) = v;
            }
            if (row8 < M) {
                float2 v = make_float2(acc[mf][nf][2] * s1, acc[mf][nf][3] * s1);
                *reinterpret_cast<float2*>(&H[(size_t)row8 * N + col]) = v;
            }
        }
    }
}

// ============================ CSR gather-aggregate (round-5 exact) ============================
template <int WIDTH, bool RELU, bool ROUND_OUT>
__global__ void aggregate_kernel(const float* __restrict__ H,
                                 const float* __restrict__ bias,
                                 float* __restrict__ out) {
    int n = blockIdx.x;
    int c = threadIdx.x * 4;
    float4 acc = make_float4(0.f, 0.f, 0.f, 0.f);
    int e0 = g_row_ptr[n];
    int e1 = g_row_ptr[n + 1];
    for (int e = e0; e < e1; e++) {
        int s = g_esrc[e];
        float4 v = *reinterpret_cast<const float4*>(&H[(size_t)s * WIDTH + c]);
        acc.x += v.x; acc.y += v.y; acc.z += v.z; acc.w += v.w;
    }
    float inn = g_in_norm[n];
    float4 b = *reinterpret_cast<const float4*>(&bias[c]);
    float4 r;
    r.x = acc.x * inn + b.x;
    r.y = acc.y * inn + b.y;
    r.z = acc.z * inn + b.z;
    r.w = acc.w * inn + b.w;
    if (RELU) {
        r.x = fmaxf(r.x, 0.f); r.y = fmaxf(r.y, 0.f);
        r.z = fmaxf(r.z, 0.f); r.w = fmaxf(r.w, 0.f);
    }
    if (ROUND_OUT) {
        r.x = rna_tf32(r.x); r.y = rna_tf32(r.y);
        r.z = rna_tf32(r.z); r.w = rna_tf32(r.w);
    }
    *reinterpret_cast<float4*>(&out[(size_t)n * WIDTH + c]) = r;
}

// ============================ launch ============================
extern "C" void kernel_launch(void* const* d_in, const int* in_sizes, int n_in,
                              void* d_out, int out_size) {
    const float* feat = (const float*)d_in[0];
    const void*  src  = d_in[1];
    const void*  dst  = d_in[2];
    const float* W0   = (const float*)d_in[3];
    const float* b0   = (const float*)d_in[4];
    const float* W1   = (const float*)d_in[5];
    const float* b1   = (const float*)d_in[6];
    const float* W2   = (const float*)d_in[7];
    const float* b2   = (const float*)d_in[8];
    float* out = (float*)d_out;

    float *pH, *pX, *pWt0, *pWt1, *pWt2;
    cudaGetSymbolAddress((void**)&pH, g_H);
    cudaGetSymbolAddress((void**)&pX, g_X);
    cudaGetSymbolAddress((void**)&pWt0, g_Wt0);
    cudaGetSymbolAddress((void**)&pWt1, g_Wt1);
    cudaGetSymbolAddress((void**)&pWt2, g_Wt2);

    cudaFuncSetAttribute(gemm_tf32_mma<true>,  cudaFuncAttributeMaxDynamicSharedMemorySize, SMEM_GEMM);
    cudaFuncSetAttribute(gemm_tf32_mma<false>, cudaFuncAttributeMaxDynamicSharedMemorySize, SMEM_GEMM);

    static cudaStream_t s2 = nullptr;
    static cudaEvent_t evDeg = nullptr, evJoin = nullptr;
    if (!s2) {
        cudaStreamCreateWithFlags(&s2, cudaStreamNonBlocking);
        cudaEventCreateWithFlags(&evDeg, cudaEventDisableTiming);
        cudaEventCreateWithFlags(&evJoin, cudaEventDisableTiming);
    }

    int mtiles = (N_NODES + 255) / 256;   // 196

    // enqueue idx 0..2: prep that gemm0 needs (epilogue reads g_cnt_out directly)
    transpose_all_kernel<<<dim3(16, 16, 3), dim3(32, 8)>>>(W0, pWt0, W1, pWt1, W2, pWt2);
    detect_zero_kernel<<<(N_NODES + 255) / 256, 256>>>((const int*)src);
    degree_kernel<<<512, 256>>>(src, dst);
    cudaEventRecord(evDeg, 0);

    // enqueue idx 3: gemm0 (ncu captures enqueue index 3)
    gemm_tf32_mma<true><<<dim3(4, mtiles), 256, SMEM_GEMM>>>(feat, pWt0, pH, N_NODES, 512);

    // side stream: norm_scan + fill hidden under gemm0 (depend only on degrees)
    cudaStreamWaitEvent(s2, evDeg, 0);
    norm_scan_kernel<<<1, 1024, 0, s2>>>();
    fill_kernel<<<512, 256, 0, s2>>>(src, dst);
    cudaEventRecord(evJoin, s2);
    cudaStreamWaitEvent(0, evJoin, 0);

    // layer 0 aggregate
    aggregate_kernel<512, true, true><<<N_NODES, 128>>>(pH, b0, pX);

    // layer 1
    gemm_tf32_mma<false><<<dim3(4, mtiles), 256, SMEM_GEMM>>>(pX, pWt1, pH, N_NODES, 512);
    aggregate_kernel<512, true, true><<<N_NODES, 128>>>(pH, b1, pX);

    // layer 2: hidden(512) -> out(256)
    gemm_tf32_mma<false><<<dim3(2, mtiles), 256, SMEM_GEMM>>>(pX, pWt2, pH, N_NODES, 256);
    aggregate_kernel<256, false, false><<<N_NODES, 64>>>(pH, b2, out);
}

// round 13
// speedup vs baseline: 1.3602x; 1.3602x over previous
#include <cuda_runtime.h>
#include <cuda_fp16.h>
#include <cuda_bf16.h>
#include <cstdint>

#define N_NODES 50000
#define N_EDGES 800000
#define F_DIM   512
#define F_OUT   256

// ---------------- persistent device scratch ----------------
__device__ float  g_H[(size_t)N_NODES * F_DIM];     // GEMM output (fp32 — precision-critical)
__device__ __half g_Xh[(size_t)N_NODES * F_DIM];    // GEMM input activations (fp16)
__device__ __half g_Wt0[512 * 512];                 // transposed weights fp16: Wt[n][k]
__device__ __half g_Wt1[512 * 512];
__device__ __half g_Wt2[512 * 256];
__device__ int    g_cnt_out[N_NODES];
__device__ int    g_cnt_in[N_NODES];
__device__ float  g_in_norm[N_NODES];
__device__ int    g_row_ptr[N_NODES + 1];
__device__ int    g_cursor[N_NODES];
__device__ int    g_esrc[N_EDGES];
__device__ int    g_is64;

__device__ __forceinline__ int load_idx(const void* p, int i) {
    if (g_is64) return (int)((const long long*)p)[i];
    return ((const int*)p)[i];
}

// ============== prep: all 3 weight transposes (fp32 -> fp16) ==============
// Wt[n*512 + k] = half(W[k*N + n])
__global__ void transpose_all_kernel(const float* __restrict__ W0, __half* __restrict__ Wt0,
                                     const float* __restrict__ W1, __half* __restrict__ Wt1,
                                     const float* __restrict__ W2, __half* __restrict__ Wt2) {
    const float* W; __half* Wt; int N;
    if (blockIdx.z == 0)      { W = W0; Wt = Wt0; N = 512; }
    else if (blockIdx.z == 1) { W = W1; Wt = Wt1; N = 512; }
    else                      { W = W2; Wt = Wt2; N = 256; if ((int)blockIdx.x >= 8) return; }
    __shared__ float tile[32][33];
    int n = blockIdx.x * 32 + threadIdx.x;
    int k = blockIdx.y * 32 + threadIdx.y;
    #pragma unroll
    for (int dy = 0; dy < 32; dy += 8)
        tile[threadIdx.y + dy][threadIdx.x] = W[(size_t)(k + dy) * N + n];
    __syncthreads();
    int n2 = blockIdx.x * 32 + threadIdx.y;
    int k2 = blockIdx.y * 32 + threadIdx.x;
    #pragma unroll
    for (int dy = 0; dy < 32; dy += 8)
        Wt[(size_t)(n2 + dy) * 512 + k2] = __float2half_rn(tile[threadIdx.x][threadIdx.y + dy]);
}

// ============== prep: detect dtype + zero counts + feat->fp16 ==============
__global__ void detect_zero_cvt_kernel(const int* p, const float* __restrict__ feat,
                                       __half* __restrict__ Xh) {
    int i = blockIdx.x * blockDim.x + threadIdx.x;
    int stride = gridDim.x * blockDim.x;
    for (int j = i; j < N_NODES; j += stride) { g_cnt_out[j] = 0; g_cnt_in[j] = 0; }
    if (i == 0) {
        int all0 = 1;
        for (int j = 1; j < 256; j += 2)
            if (p[j] != 0) { all0 = 0; break; }
        g_is64 = all0;
    }
    const size_t total = (size_t)N_NODES * F_DIM / 4;
    for (size_t j = i; j < total; j += stride) {
        float4 v = reinterpret_cast<const float4*>(feat)[j];
        __half2 h0 = __floats2half2_rn(v.x, v.y);
        __half2 h1 = __floats2half2_rn(v.z, v.w);
        uint2 u;
        u.x = *reinterpret_cast<uint32_t*>(&h0);
        u.y = *reinterpret_cast<uint32_t*>(&h1);
        reinterpret_cast<uint2*>(Xh)[j] = u;
    }
}

// ============== prep: degrees ==============
__global__ void degree_kernel(const void* src, const void* dst) {
    int stride = gridDim.x * blockDim.x;
    for (int e = blockIdx.x * blockDim.x + threadIdx.x; e < N_EDGES; e += stride) {
        atomicAdd(&g_cnt_out[load_idx(src, e)], 1);
        atomicAdd(&g_cnt_in[load_idx(dst, e)], 1);
    }
}

// ============== prep: in_norm + row_ptr scan (1 block, 1024 thr) ==============
__global__ void norm_scan_kernel() {
    const int PER = (N_NODES + 1023) / 1024;   // 49
    __shared__ int wsum[32];
    int t = threadIdx.x;
    int lane = t & 31, wid = t >> 5;
    int start = t * PER;
    int end = start + PER; if (end > N_NODES) end = N_NODES;

    int sum = 0;
    for (int i = start; i < end; i++) {
        int ci = g_cnt_in[i]; if (ci < 1) ci = 1;
        g_in_norm[i] = rsqrtf((float)ci);
        sum += g_cnt_in[i];
    }
    int v = sum;
    #pragma unroll
    for (int o = 1; o < 32; o <<= 1) {
        int u = __shfl_up_sync(0xFFFFFFFFu, v, o);
        if (lane >= o) v += u;
    }
    if (lane == 31) wsum[wid] = v;
    __syncthreads();
    if (wid == 0) {
        int w = wsum[lane];
        #pragma unroll
        for (int o = 1; o < 32; o <<= 1) {
            int u = __shfl_up_sync(0xFFFFFFFFu, w, o);
            if (lane >= o) w += u;
        }
        wsum[lane] = w;
    }
    __syncthreads();
    int base = (wid > 0) ? wsum[wid - 1] : 0;
    int run = base + v - sum;
    for (int i = start; i < end; i++) {
        g_row_ptr[i] = run;
        g_cursor[i]  = run;
        run += g_cnt_in[i];
    }
    if (t == 1023) g_row_ptr[N_NODES] = run;
}

// ============== prep: CSR fill ==============
__global__ void fill_kernel(const void* src, const void* dst) {
    int stride = gridDim.x * blockDim.x;
    for (int e = blockIdx.x * blockDim.x + threadIdx.x; e < N_EDGES; e += stride) {
        int d = load_idx(dst, e);
        int pos = atomicAdd(&g_cursor[d], 1);
        g_esrc[pos] = load_idx(src, e);
    }
}

// ============================ fp16 mma.sync GEMM ============================
// H[m, n] = (sum_k Xh[m,k] * Wt[n,k]) * rsqrt(max(cnt_out[m],1))   (fp32 accumulate)
// BM=256, BN=128, BK=64 fp16, 256 thr, warp grid 4x2, warp tile 64x64,
// m16n8k16 HMMA, LDSM frags, 2-stage cp.async (row-10 proven pipeline shape).
#define BKH       64                          // fp16 per K chunk (128B rows)
#define ROW_HB    144                         // row stride bytes (128B data + 16B pad)
#define A_BYTES_H (256 * ROW_HB)              // 36864
#define B_BYTES_H (128 * ROW_HB)              // 18432
#define STAGE_BYTES_H (A_BYTES_H + B_BYTES_H) // 55296
#define SMEM_GEMM (2 * STAGE_BYTES_H)         // 110592

__device__ __forceinline__ uint32_t smem_u32(const void* p) {
    uint32_t a;
    asm("{ .reg .u64 t; cvta.to.shared.u64 t, %1; cvt.u32.u64 %0, t; }" : "=r"(a) : "l"(p));
    return a;
}
__device__ __forceinline__ void cp_async16(uint32_t dst, const void* src) {
    asm volatile("cp.async.ca.shared.global [%0], [%1], 16;" :: "r"(dst), "l"(src));
}
__device__ __forceinline__ void ldsm_x4(uint32_t& r0, uint32_t& r1, uint32_t& r2, uint32_t& r3,
                                        uint32_t addr) {
    asm volatile("ldmatrix.sync.aligned.m8n8.x4.shared.b16 {%0,%1,%2,%3}, [%4];"
        : "=r"(r0), "=r"(r1), "=r"(r2), "=r"(r3) : "r"(addr));
}
__device__ __forceinline__ void mma_f16(float c[4],
                                        uint32_t a0, uint32_t a1, uint32_t a2, uint32_t a3,
                                        uint32_t b0, uint32_t b1) {
    asm volatile("mma.sync.aligned.m16n8k16.row.col.f32.f16.f16.f32 "
        "{%0,%1,%2,%3}, {%4,%5,%6,%7}, {%8,%9}, {%0,%1,%2,%3};"
        : "+f"(c[0]), "+f"(c[1]), "+f"(c[2]), "+f"(c[3])
        : "r"(a0), "r"(a1), "r"(a2), "r"(a3), "r"(b0), "r"(b1));
}
__device__ __forceinline__ float out_norm_of(int row) {
    int co = g_cnt_out[row]; if (co < 1) co = 1;
    return rsqrtf((float)co);
}

__global__ __launch_bounds__(256)
void gemm_f16_mma(const __half* __restrict__ X, const __half* __restrict__ Wt,
                  float* __restrict__ H, int M, int N) {
    extern __shared__ __half smemh[];
    uint32_t sbase = smem_u32(smemh);
    int tid  = threadIdx.x;
    int wid  = tid >> 5;
    int lane = tid & 31;
    int m0 = blockIdx.y * 256;
    int n0 = blockIdx.x * 128;

    int wm = wid >> 1;       // 0..3 -> 64-row m tiles
    int wn = wid & 1;        // 0..1 -> 64-col n tiles
    int qrow = lane >> 2;
    int qk   = lane & 3;

    int cr = tid >> 3;       // 0..31
    int cc = tid & 7;        // 16B column (8 fp16)

    // LDSM per-lane byte offsets within a stage:
    // lanes 0-15 -> rows (lane&15), lanes 16-31 -> same rows, k+8 halves (16B)
    uint32_t pa_off = (uint32_t)((wm * 64 + (lane & 15)) * ROW_HB + (lane >> 4) * 16);
    uint32_t pb_off = (uint32_t)((wn * 64 + (lane & 15)) * ROW_HB + (lane >> 4) * 16)
                      + A_BYTES_H;

    float acc[4][8][4];
    #pragma unroll
    for (int i = 0; i < 4; i++)
        #pragma unroll
        for (int j = 0; j < 8; j++)
            #pragma unroll
            for (int q = 0; q < 4; q++) acc[i][j][q] = 0.f;

    const int n_chunks = 512 / BKH;   // 8

    // prefetch chunk 0 -> stage 0
    {
        uint32_t aS = sbase;
        uint32_t bS = sbase + A_BYTES_H;
        #pragma unroll
        for (int pass = 0; pass < 8; pass++) {
            int r = cr + pass * 32;
            int grow = m0 + r;
            uint32_t adst = aS + (uint32_t)(r * ROW_HB + cc * 16);
            if (grow < M) cp_async16(adst, &X[(size_t)grow * 512 + cc * 8]);
            else *reinterpret_cast<float4*>(&smemh[(r * ROW_HB + cc * 16) / 2]) =
                     make_float4(0.f, 0.f, 0.f, 0.f);
        }
        #pragma unroll
        for (int pass = 0; pass < 4; pass++) {
            int r = cr + pass * 32;
            uint32_t bdst = bS + (uint32_t)(r * ROW_HB + cc * 16);
            cp_async16(bdst, &Wt[(size_t)(n0 + r) * 512 + cc * 8]);
        }
        asm volatile("cp.async.commit_group;");
    }

    for (int i = 0; i < n_chunks; i++) {
        if (i + 1 < n_chunks) {
            int k0 = (i + 1) * BKH;
            int st = (i + 1) & 1;
            uint32_t aS = sbase + (uint32_t)(st * STAGE_BYTES_H);
            uint32_t bS = aS + A_BYTES_H;
            __half* aF = smemh + (size_t)st * STAGE_BYTES_H / 2;
            #pragma unroll
            for (int pass = 0; pass < 8; pass++) {
                int r = cr + pass * 32;
                int grow = m0 + r;
                uint32_t adst = aS + (uint32_t)(r * ROW_HB + cc * 16);
                if (grow < M) cp_async16(adst, &X[(size_t)grow * 512 + k0 + cc * 8]);
                else *reinterpret_cast<float4*>(&aF[(r * ROW_HB + cc * 16) / 2]) =
                         make_float4(0.f, 0.f, 0.f, 0.f);
            }
            #pragma unroll
            for (int pass = 0; pass < 4; pass++) {
                int r = cr + pass * 32;
                uint32_t bdst = bS + (uint32_t)(r * ROW_HB + cc * 16);
                cp_async16(bdst, &Wt[(size_t)(n0 + r) * 512 + k0 + cc * 8]);
            }
            asm volatile("cp.async.commit_group;");
            asm volatile("cp.async.wait_group 1;");
        } else {
            asm volatile("cp.async.wait_group 0;");
        }
        __syncthreads();

        uint32_t stage = (uint32_t)((i & 1) * STAGE_BYTES_H);
        uint32_t paS = sbase + stage + pa_off;
        uint32_t pbS = sbase + stage + pb_off;

        #pragma unroll
        for (int ks = 0; ks < 4; ks++) {          // 4 x k16 steps per 64-wide chunk
            uint32_t af[4][4];
            #pragma unroll
            for (int mf = 0; mf < 4; mf++)
                ldsm_x4(af[mf][0], af[mf][1], af[mf][2], af[mf][3],
                        paS + (uint32_t)(mf * 16 * ROW_HB + ks * 32));
            uint32_t bf[8][2];
            #pragma unroll
            for (int f = 0; f < 4; f++) {
                uint32_t r0, r1, r2, r3;
                ldsm_x4(r0, r1, r2, r3, pbS + (uint32_t)(f * 16 * ROW_HB + ks * 32));
                // r0=(n0-7,k0-7) r1=(n8-15,k0-7) r2=(n0-7,k8-15) r3=(n8-15,k8-15)
                bf[2*f][0] = r0; bf[2*f][1] = r2;
                bf[2*f+1][0] = r1; bf[2*f+1][1] = r3;
            }
            #pragma unroll
            for (int mf = 0; mf < 4; mf++)
                #pragma unroll
                for (int nf = 0; nf < 8; nf++)
                    mma_f16(acc[mf][nf], af[mf][0], af[mf][1], af[mf][2], af[mf][3],
                            bf[nf][0], bf[nf][1]);
        }
    }

    // epilogue: scale by out_norm (inline from degree counters), fp32 store
    #pragma unroll
    for (int mf = 0; mf < 4; mf++) {
        int row  = m0 + wm * 64 + mf * 16 + qrow;
        int row8 = row + 8;
        float s0 = (row  < M) ? out_norm_of(row)  : 0.f;
        float s1 = (row8 < M) ? out_norm_of(row8) : 0.f;
        #pragma unroll
        for (int nf = 0; nf < 8; nf++) {
            int col = n0 + wn * 64 + nf * 8 + qk * 2;
            if (row < M) {
                float2 v = make_float2(acc[mf][nf][0] * s0, acc[mf][nf][1] * s0);
                *reinterpret_cast<float2*>(&H[(size_t)row * N + col]) = v;
            }
            if (row8 < M) {
                float2 v = make_float2(acc[mf][nf][2] * s1, acc[mf][nf][3] * s1);
                *reinterpret_cast<float2*>(&H[(size_t)row8 * N + col]) = v;
            }
        }
    }
}

// ============================ CSR gather-aggregate ============================
// fp32 H gather (precision-critical), fp32 accumulate; output fp16 (next GEMM) or fp32 (final).
template <int WIDTH, bool RELU, bool OUT_HALF>
__global__ void aggregate_kernel(const float* __restrict__ H,
                                 const float* __restrict__ bias,
                                 void* __restrict__ outv) {
    int n = blockIdx.x;
    int c = threadIdx.x * 4;
    float4 acc = make_float4(0.f, 0.f, 0.f, 0.f);
    int e0 = g_row_ptr[n];
    int e1 = g_row_ptr[n + 1];
    for (int e = e0; e < e1; e++) {
        int s = g_esrc[e];
        float4 v = *reinterpret_cast<const float4*>(&H[(size_t)s * WIDTH + c]);
        acc.x += v.x; acc.y += v.y; acc.z += v.z; acc.w += v.w;
    }
    float inn = g_in_norm[n];
    float4 b = *reinterpret_cast<const float4*>(&bias[c]);
    float4 r;
    r.x = acc.x * inn + b.x;
    r.y = acc.y * inn + b.y;
    r.z = acc.z * inn + b.z;
    r.w = acc.w * inn + b.w;
    if (RELU) {
        r.x = fmaxf(r.x, 0.f); r.y = fmaxf(r.y, 0.f);
        r.z = fmaxf(r.z, 0.f); r.w = fmaxf(r.w, 0.f);
    }
    if (OUT_HALF) {
        __half2 h0 = __floats2half2_rn(r.x, r.y);
        __half2 h1 = __floats2half2_rn(r.z, r.w);
        uint2 u;
        u.x = *reinterpret_cast<uint32_t*>(&h0);
        u.y = *reinterpret_cast<uint32_t*>(&h1);
        *reinterpret_cast<uint2*>(&((__half*)outv)[(size_t)n * WIDTH + c]) = u;
    } else {
        *reinterpret_cast<float4*>(&((float*)outv)[(size_t)n * WIDTH + c]) = r;
    }
}

// ============================ launch ============================
extern "C" void kernel_launch(void* const* d_in, const int* in_sizes, int n_in,
                              void* d_out, int out_size) {
    const float* feat = (const float*)d_in[0];
    const void*  src  = d_in[1];
    const void*  dst  = d_in[2];
    const float* W0   = (const float*)d_in[3];
    const float* b0   = (const float*)d_in[4];
    const float* W1   = (const float*)d_in[5];
    const float* b1   = (const float*)d_in[6];
    const float* W2   = (const float*)d_in[7];
    const float* b2   = (const float*)d_in[8];
    float* out = (float*)d_out;

    float* pH;
    __half *pXh, *pWt0, *pWt1, *pWt2;
    cudaGetSymbolAddress((void**)&pH, g_H);
    cudaGetSymbolAddress((void**)&pXh, g_Xh);
    cudaGetSymbolAddress((void**)&pWt0, g_Wt0);
    cudaGetSymbolAddress((void**)&pWt1, g_Wt1);
    cudaGetSymbolAddress((void**)&pWt2, g_Wt2);

    cudaFuncSetAttribute(gemm_f16_mma, cudaFuncAttributeMaxDynamicSharedMemorySize, SMEM_GEMM);

    static cudaStream_t s2 = nullptr;
    static cudaEvent_t evDeg = nullptr, evJoin = nullptr;
    if (!s2) {
        cudaStreamCreateWithFlags(&s2, cudaStreamNonBlocking);
        cudaEventCreateWithFlags(&evDeg, cudaEventDisableTiming);
        cudaEventCreateWithFlags(&evJoin, cudaEventDisableTiming);
    }

    int mtiles = (N_NODES + 255) / 256;   // 196

    // enqueue idx 0..2: prep that gemm0 needs
    transpose_all_kernel<<<dim3(16, 16, 3), dim3(32, 8)>>>(W0, pWt0, W1, pWt1, W2, pWt2);
    detect_zero_cvt_kernel<<<1024, 256>>>((const int*)src, feat, pXh);
    degree_kernel<<<512, 256>>>(src, dst);
    cudaEventRecord(evDeg, 0);

    // enqueue idx 3: gemm0 (ncu captures enqueue index 3)
    gemm_f16_mma<<<dim3(4, mtiles), 256, SMEM_GEMM>>>(pXh, pWt0, pH, N_NODES, 512);

    // side stream: norm_scan + fill hidden under gemm0 (depend only on degrees)
    cudaStreamWaitEvent(s2, evDeg, 0);
    norm_scan_kernel<<<1, 1024, 0, s2>>>();
    fill_kernel<<<512, 256, 0, s2>>>(src, dst);
    cudaEventRecord(evJoin, s2);
    cudaStreamWaitEvent(0, evJoin, 0);

    // layer 0 aggregate -> fp16 X
    aggregate_kernel<512, true, true><<<N_NODES, 128>>>(pH, b0, pXh);

    // layer 1
    gemm_f16_mma<<<dim3(4, mtiles), 256, SMEM_GEMM>>>(pXh, pWt1, pH, N_NODES, 512);
    aggregate_kernel<512, true, true><<<N_NODES, 128>>>(pH, b1, pXh);

    // layer 2: hidden(512) -> out(256), fp32 output
    gemm_f16_mma<<<dim3(2, mtiles), 256, SMEM_GEMM>>>(pXh, pWt2, pH, N_NODES, 256);
    aggregate_kernel<256, false, false><<<N_NODES, 64>>>(pH, b2, out);
}